// round 17
// baseline (speedup 1.0000x reference)
#include <cuda_runtime.h>
#include <cuda_fp16.h>
#include <cstdint>

// Causal prefill attention, q,k,v,out: [B,H,L,D] fp32. B=2 H=16 L=2048 D=128.
// Kernel 1: convert k/v fp32 -> fp16 (RN) into static device buffers.
// Kernel 2: flash-attention-2, fp16 mma.sync.m16n8k16 (fp32 accum).
// R17: BR=64, 8 warps x 16 query rows, 2 CTAs/SM -> 4 warps/SMSP so one
// warp's softmax gaps are covered by other warps' MMAs; regs/thread <= 128.
// Warp (rg, half) = 16 query rows x 32-key half, warp-local LAZY softmax
// (frozen reference max + slack-8 ballot; rescale ~never fires), P register-
// resident (GEMM1 C-fragment packs directly into GEMM2's A-fragment),
// row-sum l via MMA-with-ones. K/V double-buffered via cp.async; Q/K/V
// operands ldmatrix-fed. Q converted + pre-scaled by log2(e)/sqrt(D) inline.

namespace {
constexpr int kL = 2048, kD = 128, kBH = 32;
constexpr int BR = 64, BC = 64, NTHR = 256;
constexpr int kN = kBH * kL * kD;
constexpr float kScaleLog2 = 0.12751745210670913f;  // (1/sqrt(128))*log2(e)
constexpr float kMInit = -60.0f;
constexpr float kLazySlack = 8.0f;       // rescale only when beaten by > 8 (p <= 256)
constexpr uint32_t ONE2 = 0x3C003C00u;   // half2(1.0, 1.0)

// fp16 smem strides (halves) and byte offsets
constexpr int TSTR = 136;   // 272 B == 16 mod 128 -> ldsm conflict-free
constexpr int B_Q  = 0;                     // 64*272 = 17408
constexpr int B_K0 = 17408;
constexpr int B_K1 = 34816;
constexpr int B_V0 = 52224;
constexpr int B_V1 = 69632;
constexpr int B_ML = 87040;                 // 256 f32 = 1024
constexpr int SMEM_BYTES = 88064;           // x2 CTAs = 176128 <= 228KB/SM
constexpr int B_MRG = B_K0;                 // epilogue merge: 33792 B, fits K0+K1
}

__device__ __half g_k16[kN];
__device__ __half g_v16[kN];

__global__ void convert_kv_f16(const float* __restrict__ k,
                               const float* __restrict__ v) {
    int i = blockIdx.x * blockDim.x + threadIdx.x;   // 0 .. kN/4-1
    float4 a = reinterpret_cast<const float4*>(k)[i];
    float4 b = reinterpret_cast<const float4*>(v)[i];
    __half2 a0 = __floats2half2_rn(a.x, a.y), a1 = __floats2half2_rn(a.z, a.w);
    __half2 b0 = __floats2half2_rn(b.x, b.y), b1 = __floats2half2_rn(b.z, b.w);
    uint2 wa, wb;
    wa.x = *reinterpret_cast<uint32_t*>(&a0); wa.y = *reinterpret_cast<uint32_t*>(&a1);
    wb.x = *reinterpret_cast<uint32_t*>(&b0); wb.y = *reinterpret_cast<uint32_t*>(&b1);
    reinterpret_cast<uint2*>(g_k16)[i] = wa;
    reinterpret_cast<uint2*>(g_v16)[i] = wb;
}

__device__ __forceinline__ float fast_ex2(float x) {
    float y;
    asm("ex2.approx.f32 %0, %1;" : "=f"(y) : "f"(x));
    return y;
}
__device__ __forceinline__ uint32_t smem_u32(const void* p) {
    uint32_t a;
    asm("{ .reg .u64 t; cvta.to.shared.u64 t, %1; cvt.u32.u64 %0, t; }" : "=r"(a) : "l"(p));
    return a;
}
__device__ __forceinline__ void ldsm_x4(uint32_t r[4], uint32_t addr) {
    asm volatile("ldmatrix.sync.aligned.m8n8.x4.shared.b16 {%0,%1,%2,%3}, [%4];"
                 : "=r"(r[0]), "=r"(r[1]), "=r"(r[2]), "=r"(r[3]) : "r"(addr));
}
__device__ __forceinline__ void ldsm_x4_t(uint32_t r[4], uint32_t addr) {
    asm volatile("ldmatrix.sync.aligned.m8n8.x4.trans.shared.b16 {%0,%1,%2,%3}, [%4];"
                 : "=r"(r[0]), "=r"(r[1]), "=r"(r[2]), "=r"(r[3]) : "r"(addr));
}
__device__ __forceinline__ void mma_f16(float c[4], const uint32_t a[4],
                                        uint32_t b0, uint32_t b1) {
    asm volatile(
        "mma.sync.aligned.m16n8k16.row.col.f32.f16.f16.f32 "
        "{%0,%1,%2,%3}, {%4,%5,%6,%7}, {%8,%9}, {%0,%1,%2,%3};\n"
        : "+f"(c[0]), "+f"(c[1]), "+f"(c[2]), "+f"(c[3])
        : "r"(a[0]), "r"(a[1]), "r"(a[2]), "r"(a[3]), "r"(b0), "r"(b1));
}

// async-stage one 64x128 fp16 tile (16B copies)
__device__ __forceinline__ void stage_tile16(uint32_t dst, const __half* __restrict__ src,
                                             int k0, int tid) {
    #pragma unroll
    for (int i = 0; i < 4; ++i) {
        int lin = tid + i * NTHR;
        int r = lin >> 4, c = lin & 15;
        const __half* p = src + (size_t)(k0 + r) * kD + c * 8;
        uint32_t d = dst + (uint32_t)(r * (TSTR * 2) + c * 16);
        asm volatile("cp.async.ca.shared.global [%0], [%1], 16;" :: "r"(d), "l"(p));
    }
}

__global__ __launch_bounds__(NTHR, 2)
void fa_f16_kernel(const float* __restrict__ gqf, float* __restrict__ gout) {
    extern __shared__ char smem[];
    const uint32_t sb = smem_u32(smem);
    float* MLp = reinterpret_cast<float*>(smem + B_ML);
    float* MRG = reinterpret_cast<float*>(smem + B_MRG);

    const int tid  = threadIdx.x;
    const int lane = tid & 31;
    const int wid  = tid >> 5;           // 0..7
    const int rg   = wid >> 1;           // row-group 0..3 (16 rows each)
    const int half = wid & 1;            // key half within each BC tile
    const int g    = lane >> 2;
    const int lq   = lane & 3;
    const int l15  = lane & 15;

    // ---- ldmatrix base addresses (bytes) ----
    const int chi = (lane >> 4) & 1;
    const uint32_t qA0 = sb + B_Q + (uint32_t)((16 * rg + l15) * (TSTR * 2) + chi * 16);
    const uint32_t krel = (uint32_t)((32 * half + ((lane >> 4) << 3) + (lane & 7)) * (TSTR * 2)
                                     + ((lane >> 3) & 1) * 16);
    const uint32_t vrel = (uint32_t)((32 * half + l15) * (TSTR * 2) + ((lane >> 4) & 1) * 16);

    const int it = (int)gridDim.x - 1 - (int)blockIdx.x;   // heavy tiles first
    const int bh = blockIdx.y;
    const size_t base = (size_t)bh * kL * kD;
    const int q0 = it * BR;
    const __half* gk = g_k16 + base;
    const __half* gv = g_v16 + base;

    // ---- prologue: stage K(0)/V(0) async; convert+prescale Q inline ----
    stage_tile16(sb + B_K0, gk, 0, tid);
    stage_tile16(sb + B_V0, gv, 0, tid);
    asm volatile("cp.async.commit_group;" ::: "memory");

    {
        __half* Qh = reinterpret_cast<__half*>(smem + B_Q);
        const float* qsrc = gqf + base;
        #pragma unroll
        for (int i = 0; i < 8; ++i) {        // 64x128 f32 -> fp16 (prescaled)
            int lin = tid + i * NTHR;
            int r = lin >> 5, c4 = (lin & 31) << 2;
            float4 t = *reinterpret_cast<const float4*>(&qsrc[(size_t)(q0 + r) * kD + c4]);
            __half2 h0 = __floats2half2_rn(t.x * kScaleLog2, t.y * kScaleLog2);
            __half2 h1 = __floats2half2_rn(t.z * kScaleLog2, t.w * kScaleLog2);
            uint2 w;
            w.x = *reinterpret_cast<uint32_t*>(&h0);
            w.y = *reinterpret_cast<uint32_t*>(&h1);
            *reinterpret_cast<uint2*>(&Qh[r * TSTR + c4]) = w;
        }
    }

    float o[16][4];
    #pragma unroll
    for (int jn = 0; jn < 16; ++jn)
        { o[jn][0] = o[jn][1] = o[jn][2] = o[jn][3] = 0.f; }
    float lacc[4] = {0.f, 0.f, 0.f, 0.f};    // row-sum fragment (MMA-with-ones)
    float mm0 = kMInit, mm1 = kMInit;        // frozen reference maxes (rows g, g+8)

    const int njt = it + 1;
    for (int jt = 0; jt < njt; ++jt) {
        const int k0 = jt * BC;

        asm volatile("cp.async.wait_group 0;" ::: "memory");   // K(jt),V(jt) resident
        __syncthreads();   // also covers Q visibility on jt==0

        if (jt + 1 < njt) {
            stage_tile16(sb + ((jt & 1) ? B_K0 : B_K1), gk, k0 + BC, tid);
            stage_tile16(sb + ((jt & 1) ? B_V0 : B_V1), gv, k0 + BC, tid);
            asm volatile("cp.async.commit_group;" ::: "memory");
        }

        const uint32_t kB = sb + (uint32_t)((jt & 1) ? B_K1 : B_K0) + krel;
        const uint32_t vB = sb + (uint32_t)((jt & 1) ? B_V1 : B_V0) + vrel;

        // ---- GEMM1: S[16 x 32] = Q' x K(half)^T (already log2-scaled) ----
        float s[4][4];
        #pragma unroll
        for (int j = 0; j < 4; ++j)
            { s[j][0] = s[j][1] = s[j][2] = s[j][3] = 0.f; }

        #pragma unroll
        for (int kk = 0; kk < 8; ++kk) {
            uint32_t A0[4], B0[4], B1[4];
            ldsm_x4(A0, qA0 + kk * 32u);
            ldsm_x4(B0, kB + kk * 32u);
            ldsm_x4(B1, kB + 16u * (TSTR * 2) + kk * 32u);
            mma_f16(s[0], A0, B0[0], B0[1]);
            mma_f16(s[1], A0, B0[2], B0[3]);
            mma_f16(s[2], A0, B1[0], B1[1]);
            mma_f16(s[3], A0, B1[2], B1[3]);
        }

        // ---- warp-local LAZY softmax (log2 domain); P packed to A-fragments ----
        const bool diag = (jt == it);
        uint32_t pa[2][4];   // [key chunk kk][a0..a3]
        {
            const int r0 = q0 + 16 * rg + g, r1 = r0 + 8;
            float t0 = -1e30f, t1 = -1e30f;
            #pragma unroll
            for (int j = 0; j < 4; ++j) {
                if (diag) {
                    int col = k0 + 32 * half + 8 * j + 2 * lq;
                    if (col     > r0) s[j][0] = -1e30f;
                    if (col + 1 > r0) s[j][1] = -1e30f;
                    if (col     > r1) s[j][2] = -1e30f;
                    if (col + 1 > r1) s[j][3] = -1e30f;
                }
                t0 = fmaxf(t0, fmaxf(s[j][0], s[j][1]));
                t1 = fmaxf(t1, fmaxf(s[j][2], s[j][3]));
            }

            // rescale only if this tile beats the frozen reference by > slack
            const bool exceed = (t0 > mm0 + kLazySlack) || (t1 > mm1 + kLazySlack);
            if (__any_sync(0xffffffffu, exceed)) {
                t0 = fmaxf(t0, __shfl_xor_sync(0xffffffffu, t0, 1));
                t0 = fmaxf(t0, __shfl_xor_sync(0xffffffffu, t0, 2));
                t1 = fmaxf(t1, __shfl_xor_sync(0xffffffffu, t1, 1));
                t1 = fmaxf(t1, __shfl_xor_sync(0xffffffffu, t1, 2));
                const float mn0 = fmaxf(mm0, t0), mn1 = fmaxf(mm1, t1);
                const float al0 = fast_ex2(mm0 - mn0), al1 = fast_ex2(mm1 - mn1);
                mm0 = mn0; mm1 = mn1;
                lacc[0] *= al0; lacc[1] *= al0;
                lacc[2] *= al1; lacc[3] *= al1;
                #pragma unroll
                for (int jn = 0; jn < 16; ++jn) {
                    o[jn][0] *= al0; o[jn][1] *= al0;
                    o[jn][2] *= al1; o[jn][3] *= al1;
                }
            }

            // exp + pack: C-fragment (rows g,g+8; cols 8j+2lq,+1) -> A-fragment
            //   chunk kk = j>>1;  j even -> a0/a1,  j odd -> a2/a3
            #pragma unroll
            for (int j = 0; j < 4; ++j) {
                float p0 = fast_ex2(s[j][0] - mm0);
                float p1 = fast_ex2(s[j][1] - mm0);
                float p2 = fast_ex2(s[j][2] - mm1);
                float p3 = fast_ex2(s[j][3] - mm1);
                __half2 h0 = __floats2half2_rn(p0, p1);   // row g
                __half2 h1 = __floats2half2_rn(p2, p3);   // row g+8
                pa[j >> 1][(j & 1) * 2]     = *reinterpret_cast<uint32_t*>(&h0);
                pa[j >> 1][(j & 1) * 2 + 1] = *reinterpret_cast<uint32_t*>(&h1);
            }
        }

        // ---- GEMM2: O[16 x 128] += P(16x32) x V(half keys); l += P x ones ----
        #pragma unroll
        for (int kk = 0; kk < 2; ++kk) {
            mma_f16(lacc, pa[kk], ONE2, ONE2);   // exact fp16 row-sums of P
            const uint32_t vkk = vB + (uint32_t)(kk * 16 * (TSTR * 2));
            #pragma unroll
            for (int jp = 0; jp < 8; ++jp) {
                uint32_t VB[4];
                ldsm_x4_t(VB, vkk + jp * 32u);
                mma_f16(o[2 * jp],     pa[kk], VB[0], VB[1]);
                mma_f16(o[2 * jp + 1], pa[kk], VB[2], VB[3]);
            }
        }
    }

    // ================= final merge of the two key-halves =================
    // ll for row-half rh lives in lacc[2*rh] (columns duplicated)
    if (lq == 0) {
        #pragma unroll
        for (int i = 0; i < 2; ++i) {
            int rloc = 16 * rg + g + 8 * i;
            MLp[half * 128 + 2 * rloc]     = (i == 0) ? mm0 : mm1;
            MLp[half * 128 + 2 * rloc + 1] = lacc[i * 2];
        }
    }
    __syncthreads();
    float coef[2];
    #pragma unroll
    for (int i = 0; i < 2; ++i) {
        int rloc = 16 * rg + g + 8 * i;
        float mi = (i == 0) ? mm0 : mm1;
        float mo = MLp[(1 - half) * 128 + 2 * rloc];
        float lo = MLp[(1 - half) * 128 + 2 * rloc + 1];
        float ms = fmaxf(mi, mo);
        float lt = lacc[i * 2] * fast_ex2(mi - ms) + lo * fast_ex2(mo - ms);
        coef[i] = fast_ex2(mi - ms) / lt;
    }
    __syncthreads();

    if (half == 0) {
        #pragma unroll
        for (int jn = 0; jn < 16; ++jn) {
            int d = 8 * jn + 2 * lq;
            int r0 = 16 * rg + g;
            MRG[r0 * 132 + d]           = o[jn][0] * coef[0];
            MRG[r0 * 132 + d + 1]       = o[jn][1] * coef[0];
            MRG[(r0 + 8) * 132 + d]     = o[jn][2] * coef[1];
            MRG[(r0 + 8) * 132 + d + 1] = o[jn][3] * coef[1];
        }
    }
    __syncthreads();
    if (half == 1) {
        const size_t gbase = (size_t)bh * kL * kD;
        #pragma unroll
        for (int jn = 0; jn < 16; ++jn) {
            int d = 8 * jn + 2 * lq;
            int r0 = 16 * rg + g;
            float2 w0, w1;
            w0.x = MRG[r0 * 132 + d]           + o[jn][0] * coef[0];
            w0.y = MRG[r0 * 132 + d + 1]       + o[jn][1] * coef[0];
            w1.x = MRG[(r0 + 8) * 132 + d]     + o[jn][2] * coef[1];
            w1.y = MRG[(r0 + 8) * 132 + d + 1] + o[jn][3] * coef[1];
            *reinterpret_cast<float2*>(&gout[gbase + (size_t)(q0 + r0) * kD + d])     = w0;
            *reinterpret_cast<float2*>(&gout[gbase + (size_t)(q0 + r0 + 8) * kD + d]) = w1;
        }
    }
}

extern "C" void kernel_launch(void* const* d_in, const int* in_sizes, int n_in,
                              void* d_out, int out_size) {
    (void)in_sizes; (void)n_in; (void)out_size;
    const float* q = (const float*)d_in[0];
    const float* k = (const float*)d_in[1];
    const float* v = (const float*)d_in[2];
    float* out = (float*)d_out;

    convert_kv_f16<<<kN / 4 / 256, 256>>>(k, v);

    cudaFuncSetAttribute(fa_f16_kernel,
                         cudaFuncAttributeMaxDynamicSharedMemorySize, SMEM_BYTES);
    dim3 grid(kL / BR, kBH);   // 32 q-tiles x 32 heads
    fa_f16_kernel<<<grid, NTHR, SMEM_BYTES>>>(q, out);
}